// round 7
// baseline (speedup 1.0000x reference)
#include <cuda_runtime.h>
#include <math.h>
#include <stdint.h>

#define BATCH   16
#define NHEADS  32
#define G       8      // kv heads
#define RQ      4      // query heads per kv head
#define D       128
#define BLK     256    // cache block size (fixed by layout)
#define MAXB    16     // cache blocks per sequence
#define CS      64     // positions per chunk CTA
#define MAXC    64     // max chunks per sequence (4096/64)
#define TS      32     // positions per tile
#define PSTR4   (G * (D / 4))   // float4 stride between positions = 256
#define RS4     33     // smem row stride in float4 (pad -> conflict-free LDS.128)
#define NEG_INF (-1e30f)
#define QK_SCALE 0.08838834764831845f  // 1/sqrt(128)

// split-KV partial results: [B, G, chunk, rq]
__device__ float g_pm  [BATCH * G * MAXC * RQ];
__device__ float g_pl  [BATCH * G * MAXC * RQ];
__device__ float g_pacc[BATCH * G * MAXC * RQ * D];

// ---- bulk-copy + mbarrier primitives ----
__device__ __forceinline__ void mbar_init(uint32_t mbar, uint32_t count) {
    asm volatile("mbarrier.init.shared.b64 [%0], %1;" :: "r"(mbar), "r"(count) : "memory");
}
__device__ __forceinline__ void mbar_expect_tx(uint32_t mbar, uint32_t bytes) {
    asm volatile("mbarrier.arrive.expect_tx.shared.b64 _, [%0], %1;"
                 :: "r"(mbar), "r"(bytes) : "memory");
}
__device__ __forceinline__ void mbar_wait(uint32_t mbar, uint32_t parity) {
    asm volatile(
        "{\n\t.reg .pred P;\n\t"
        "WAIT_%=:\n\t"
        "mbarrier.try_wait.parity.acquire.cta.shared::cta.b64 P, [%0], %1, 0x989680;\n\t"
        "@!P bra WAIT_%=;\n\t}"
        :: "r"(mbar), "r"(parity) : "memory");
}
__device__ __forceinline__ void bulk_g2s(uint32_t dst, const void* src,
                                         uint32_t bytes, uint32_t mbar) {
    asm volatile(
        "cp.async.bulk.shared::cluster.global.mbarrier::complete_tx::bytes [%0], [%1], %2, [%3];"
        :: "r"(dst), "l"(src), "r"(bytes), "r"(mbar) : "memory");
}
__device__ __forceinline__ void fence_async_proxy() {
    asm volatile("fence.proxy.async.shared::cta;" ::: "memory");
}

// smem layout (float4 units):
//   [0,    1056)  K buf 0   (32 rows x 33 f4, padded rows)
//   [1056, 2112)  K buf 1
//   [2112, 3168)  V buf 0
//   [3168, 4224)  V buf 1
//   [4224, 4352)  q   [chunk][head] float4, pre-scaled
//   [4352, 4384)  pt  [pos] float4 = 4 heads' exp weights
//   [4384, 4385)  red scratch (al[4])
//   [4385, 4386)  mbarriers (2 x 8B)
#define KB0_F4   0
#define KB1_F4   1056
#define VB0_F4   2112
#define VB1_F4   3168
#define QSM_F4   4224
#define PT_F4    4352
#define RED_F4   4384
#define MBAR_F4  4385
#define SMEM_F4  4386
#define SMEM_BYTES (SMEM_F4 * 16)   // 70176 B -> 3 CTAs/SM

__global__ __launch_bounds__(128, 3)
void attn_chunk_kernel(const float* __restrict__ q,
                       const float* __restrict__ knew,
                       const float* __restrict__ vnew,
                       const float* __restrict__ kcache,
                       const float* __restrict__ vcache,
                       const int*   __restrict__ ctx_lens,
                       const int*   __restrict__ btab,
                       const int*   __restrict__ slot_map)
{
    const int c = blockIdx.x;   // chunk (CS positions)
    const int g = blockIdx.y;   // kv head
    const int b = blockIdx.z;   // sequence

    const int ctx   = ctx_lens[b];
    const int start = c * CS;
    if (start >= ctx) return;
    const int npos = min(CS, ctx - start);

    extern __shared__ float4 sm4[];
    float4* kb[2] = { sm4 + KB0_F4, sm4 + KB1_F4 };
    float4* vb[2] = { sm4 + VB0_F4, sm4 + VB1_F4 };
    float4* qsm  = sm4 + QSM_F4;
    float4* pt   = sm4 + PT_F4;
    float*  red  = (float*)(sm4 + RED_F4);   // al[0..3]

    const uint32_t smem_base = (uint32_t)__cvta_generic_to_shared(sm4);
    const uint32_t kb_a[2] = { smem_base + KB0_F4 * 16, smem_base + KB1_F4 * 16 };
    const uint32_t vb_a[2] = { smem_base + VB0_F4 * 16, smem_base + VB1_F4 * 16 };
    const uint32_t mbar[2] = { smem_base + MBAR_F4 * 16, smem_base + MBAR_F4 * 16 + 8 };

    const int tid  = threadIdx.x;
    const int lane = tid & 31;    // position within tile (score) / V lane (PV)
    const int warp = tid >> 5;    // head (score) / position group (PV)

    // chunk c sits inside cache block start/BLK at row offset start%BLK
    const int blkid = btab[b * MAXB + (start >> 8)];
    const size_t rowbase = (size_t)blkid * BLK + (start & (BLK - 1));
    const float4* kbase = (const float4*)kcache + rowbase * PSTR4 + g * (D / 4);
    const float4* vbase = (const float4*)vcache + rowbase * PSTR4 + g * (D / 4);

    const int lastLocal = (slot_map[b] >= 0) ? (ctx - 1 - start) : -1000000;
    const float4* knp = (const float4*)knew + (size_t)(b * G + g) * (D / 4);
    const float4* vnp = (const float4*)vnew + (size_t)(b * G + g) * (D / 4);

    const int ntiles = (npos + TS - 1) / TS;   // 1 or 2

    // ---- init barriers + issue tile 0 (thread 0 only; program-ordered) ----
    if (tid == 0) {
        mbar_init(mbar[0], 1);
        mbar_init(mbar[1], 1);
        fence_async_proxy();
        const int rows = min(TS, npos);
        mbar_expect_tx(mbar[0], (uint32_t)rows * 1024u);
        for (int r = 0; r < rows; ++r) {
            bulk_g2s(kb_a[0] + (uint32_t)(r * RS4 * 16), kbase + (size_t)r * PSTR4, 512u, mbar[0]);
            bulk_g2s(vb_a[0] + (uint32_t)(r * RS4 * 16), vbase + (size_t)r * PSTR4, 512u, mbar[0]);
        }
    }

    // q into smem, pre-scaled, layout [chunk][head]
    {
        const float4* qb = (const float4*)q + (size_t)(b * NHEADS + g * RQ) * (D / 4);
        int cc = tid >> 2, h = tid & 3;
        float4 t4 = qb[h * 32 + cc];
        t4.x *= QK_SCALE; t4.y *= QK_SCALE; t4.z *= QK_SCALE; t4.w *= QK_SCALE;
        qsm[cc * 4 + h] = t4;
    }

    float4 acc0 = make_float4(0.f, 0.f, 0.f, 0.f);
    float4 acc1 = acc0, acc2 = acc0, acc3 = acc0;
    float m_run = NEG_INF, l_run = 0.f;   // per-warp (= per-head) running state

    for (int t = 0; t < ntiles; ++t) {
        const int t0 = t * TS;
        const int cur = t & 1;

        __syncthreads();   // (A) everyone done with tile t-1 buffers & pt
                           //     (also covers mbar init visibility at t=0)

        // issue tile t+1 into the other stage
        if (tid == 0 && t + 1 < ntiles) {
            const int t1 = t0 + TS;
            const int rows = min(TS, npos - t1);
            const int s1 = cur ^ 1;
            mbar_expect_tx(mbar[s1], (uint32_t)rows * 1024u);
            for (int r = 0; r < rows; ++r) {
                bulk_g2s(kb_a[s1] + (uint32_t)(r * RS4 * 16),
                         kbase + (size_t)(t1 + r) * PSTR4, 512u, mbar[s1]);
                bulk_g2s(vb_a[s1] + (uint32_t)(r * RS4 * 16),
                         vbase + (size_t)(t1 + r) * PSTR4, 512u, mbar[s1]);
            }
        }

        // wait for tile t (acquire)
        mbar_wait(mbar[cur], (t >> 1) & 1);

        // fresh-token substitution (uniform condition across CTA)
        const int fr = lastLocal - t0;
        if (fr >= 0 && fr < TS) {
            __syncthreads();
            if (tid < 32) {
                kb[cur][fr * RS4 + tid] = knp[tid];
                vb[cur][fr * RS4 + tid] = vnp[tid];
            }
            __syncthreads();
        }

        // ---- score: warp = head, lane = position ----
        const int pvn = min(TS, npos - t0);
        float s = NEG_INF;
        {
            const float4* krow = kb[cur] + lane * RS4;   // padded stride: conflict-free
            float a = 0.f;
            #pragma unroll 8
            for (int cc = 0; cc < 32; ++cc) {
                float4 k4 = krow[cc];
                float4 q4 = qsm[cc * 4 + warp];          // warp-uniform broadcast
                a += k4.x * q4.x + k4.y * q4.y + k4.z * q4.z + k4.w * q4.w;
            }
            if (lane < pvn) s = a;
        }

        // warp-local tile max (all lanes get it)
        float mt = s;
        #pragma unroll
        for (int off = 16; off > 0; off >>= 1)
            mt = fmaxf(mt, __shfl_xor_sync(0xffffffffu, mt, off));

        const float mn = fmaxf(m_run, mt);
        const float al = __expf(m_run - mn);
        m_run = mn;

        const float e = __expf(s - mn);                  // 0 for invalid lanes
        ((float*)pt)[lane * 4 + warp] = e;

        float lt = e;
        #pragma unroll
        for (int off = 16; off > 0; off >>= 1)
            lt += __shfl_xor_sync(0xffffffffu, lt, off);
        l_run = l_run * al + lt;

        if (lane == 0) red[warp] = al;
        __syncthreads();    // (C) pt + al visible

        // ---- PV: warp w owns positions w, w+4, ... ----
        {
            const float al0 = red[0], al1 = red[1], al2 = red[2], al3 = red[3];
            acc0.x *= al0; acc0.y *= al0; acc0.z *= al0; acc0.w *= al0;
            acc1.x *= al1; acc1.y *= al1; acc1.z *= al1; acc1.w *= al1;
            acc2.x *= al2; acc2.y *= al2; acc2.z *= al2; acc2.w *= al2;
            acc3.x *= al3; acc3.y *= al3; acc3.z *= al3; acc3.w *= al3;

            #pragma unroll 8
            for (int p = warp; p < pvn; p += 4) {
                float4 v4 = vb[cur][p * RS4 + lane];     // padded stride: conflict-free
                float4 p4 = pt[p];                       // broadcast
                acc0.x += p4.x * v4.x; acc0.y += p4.x * v4.y;
                acc0.z += p4.x * v4.z; acc0.w += p4.x * v4.w;
                acc1.x += p4.y * v4.x; acc1.y += p4.y * v4.y;
                acc1.z += p4.y * v4.z; acc1.w += p4.y * v4.w;
                acc2.x += p4.z * v4.x; acc2.y += p4.z * v4.y;
                acc2.z += p4.z * v4.z; acc2.w += p4.z * v4.w;
                acc3.x += p4.w * v4.x; acc3.y += p4.w * v4.y;
                acc3.z += p4.w * v4.z; acc3.w += p4.w * v4.w;
            }
        }
    }

    // ---- epilogue ----
    const size_t pidx = ((size_t)(b * G + g) * MAXC + c) * RQ;
    if (lane == 0) {                     // warp w owns head w's m/l
        g_pm[pidx + warp] = m_run;
        g_pl[pidx + warp] = l_run;
    }

    __syncthreads();
    float4* ab = sm4;   // reuse K bufs: [warp][head][lane] float4 = 512 f4
    ab[(warp * 4 + 0) * 32 + lane] = acc0;
    ab[(warp * 4 + 1) * 32 + lane] = acc1;
    ab[(warp * 4 + 2) * 32 + lane] = acc2;
    ab[(warp * 4 + 3) * 32 + lane] = acc3;
    __syncthreads();

    const float* abf = (const float*)ab;
    #pragma unroll
    for (int e = tid; e < RQ * D; e += 128) {
        int h = e >> 7, d = e & 127;
        float A = abf[(0 * 4 + h) * 128 + d] + abf[(1 * 4 + h) * 128 + d]
                + abf[(2 * 4 + h) * 128 + d] + abf[(3 * 4 + h) * 128 + d];
        g_pacc[(pidx + h) * D + d] = A;
    }
}

// combine: 256 threads; group 0 reduces chunks [0,32), group 1 [32,64)
// as ONE predicated 32-wide load batch (MLP=32); merge in smem.
__global__ __launch_bounds__(256)
void attn_combine_kernel(const int* __restrict__ ctx_lens,
                         float* __restrict__ out)
{
    const int h = blockIdx.x;   // 0..31
    const int b = blockIdx.y;   // 0..15
    const int g  = h >> 2;
    const int hh = h & 3;
    const int nc = (ctx_lens[b] + CS - 1) / CS;   // up to 64 chunks
    const int tid = threadIdx.x;
    const int grp = tid >> 7;      // 0 or 1
    const int d   = tid & 127;

    const size_t base = ((size_t)(b * G + g) * MAXC) * RQ + hh;
    const int lo = grp * 32;

    float mv[32], lv[32], av[32];
    #pragma unroll
    for (int j = 0; j < 32; ++j) {
        const int cc = lo + j;
        if (cc < nc) {
            mv[j] = g_pm[base + (size_t)cc * RQ];
            lv[j] = g_pl[base + (size_t)cc * RQ];
            av[j] = g_pacc[(base + (size_t)cc * RQ) * D + d];
        } else { mv[j] = NEG_INF; lv[j] = 0.f; av[j] = 0.f; }
    }
    float M = mv[0];
    #pragma unroll
    for (int j = 1; j < 32; ++j) M = fmaxf(M, mv[j]);
    M = fmaxf(M, NEG_INF);   // keep finite-ish
    float L = 0.f, A = 0.f;
    #pragma unroll
    for (int j = 0; j < 32; ++j) {
        const float e = __expf(mv[j] - M);
        L += e * lv[j];
        A += e * av[j];
    }

    __shared__ float sA[D];
    __shared__ float sM, sL;
    if (grp == 1) {
        sA[d] = A;
        if (d == 0) { sM = M; sL = L; }
    }
    __syncthreads();
    if (grp == 0) {
        const float M1 = sM, L1 = sL, A1 = sA[d];
        const float Mt = fmaxf(M, M1);
        const float e0 = __expf(M - Mt), e1 = __expf(M1 - Mt);
        out[((size_t)b * NHEADS + h) * D + d] =
            (A * e0 + A1 * e1) / (L * e0 + L1 * e1);
    }
}

extern "C" void kernel_launch(void* const* d_in, const int* in_sizes, int n_in,
                              void* d_out, int out_size)
{
    const float* q    = (const float*)d_in[0];
    const float* k    = (const float*)d_in[1];
    const float* v    = (const float*)d_in[2];
    const float* kc   = (const float*)d_in[3];
    const float* vc   = (const float*)d_in[4];
    const int*   ctx  = (const int*)d_in[5];
    const int*   btab = (const int*)d_in[6];
    const int*   smap = (const int*)d_in[7];
    float* out = (float*)d_out;

    static int smem_set = 0;
    if (!smem_set) {
        cudaFuncSetAttribute(attn_chunk_kernel,
                             cudaFuncAttributeMaxDynamicSharedMemorySize, SMEM_BYTES);
        smem_set = 1;
    }

    dim3 grid(MAXC, G, BATCH);   // 8192 CTAs, ~520 non-empty
    attn_chunk_kernel<<<grid, 128, SMEM_BYTES>>>(q, k, v, kc, vc, ctx, btab, smap);
    attn_combine_kernel<<<dim3(NHEADS, BATCH), 256>>>(ctx, out);
}

// round 8
// speedup vs baseline: 1.1118x; 1.1118x over previous
#include <cuda_runtime.h>
#include <math.h>
#include <stdint.h>

#define BATCH   16
#define NHEADS  32
#define G       8      // kv heads
#define RQ      4      // query heads per kv head
#define D       128
#define BLK     256    // cache block size (fixed by layout)
#define MAXB    16     // cache blocks per sequence
#define CS      64     // positions per chunk work item
#define MAXC    64     // max chunks per sequence (4096/64)
#define TS      32     // positions per tile
#define NITEMS  (MAXC * G * BATCH)   // 8192 work items
#define PSTR4   (G * (D / 4))        // float4 stride between positions = 256
#define NEG_INF (-1e30f)
#define QK_SCALE 0.08838834764831845f  // 1/sqrt(128)
#define NCTAS   444                    // 3 per SM on 148 SMs

// split-KV partial results: [B, G, chunk, rq]
__device__ float g_pm  [BATCH * G * MAXC * RQ];
__device__ float g_pl  [BATCH * G * MAXC * RQ];
__device__ float g_pacc[BATCH * G * MAXC * RQ * D];
__device__ int   g_item_ctr;
__device__ int   g_done[BATCH * G];

__device__ __forceinline__ void cp16(uint32_t dst, const void* src) {
    asm volatile("cp.async.cg.shared.global [%0], [%1], 16;" :: "r"(dst), "l"(src));
}
__device__ __forceinline__ void cp_commit() {
    asm volatile("cp.async.commit_group;");
}
template <int N>
__device__ __forceinline__ void cp_wait() {
    asm volatile("cp.async.wait_group %0;" :: "n"(N));
}

// smem layout (float4 units):
//   [0,    1024)  K buf 0   (32 rows x 32 chunks, row-XOR swizzled)
//   [1024, 2048)  K buf 1
//   [2048, 3072)  V buf 0
//   [3072, 4096)  V buf 1
//   [4096, 4224)  q   [chunk][head] float4, pre-scaled
//   [4224, 4256)  pt  [pos] float4 = 4 heads' exp weights
//   [4256, 4257)  red scratch (al[4])
//   [4257, 4258)  item slot / flag (int)
//   [4258, 4262)  ctx_lens cache (16 ints)
#define QSM_F4   4096
#define PT_F4    4224
#define RED_F4   4256
#define ITEM_F4  4257
#define CTX_F4   4258
#define SMEM_F4  4262
#define SMEM_BYTES (SMEM_F4 * 16)   // 68192 B -> 3 CTAs/SM

__global__ void reset_kernel() {
    const int t = threadIdx.x;
    if (t == 0) g_item_ctr = 0;
    if (t < BATCH * G) g_done[t] = 0;
}

__global__ __launch_bounds__(128)
void attn_persist_kernel(const float* __restrict__ q,
                         const float* __restrict__ knew,
                         const float* __restrict__ vnew,
                         const float* __restrict__ kcache,
                         const float* __restrict__ vcache,
                         const int*   __restrict__ ctx_lens,
                         const int*   __restrict__ btab,
                         const int*   __restrict__ slot_map,
                         float*       __restrict__ out)
{
    extern __shared__ float4 sm4[];
    float4* kb[2] = { sm4,        sm4 + 1024 };
    float4* vb[2] = { sm4 + 2048, sm4 + 3072 };
    float4* qsm   = sm4 + QSM_F4;
    float4* pt    = sm4 + PT_F4;
    float*  red   = (float*)(sm4 + RED_F4);
    int*    sitem = (int*)(sm4 + ITEM_F4);
    int*    sctx  = (int*)(sm4 + CTX_F4);

    const int tid  = threadIdx.x;
    const int lane = tid & 31;
    const int warp = tid >> 5;

    if (tid < BATCH) sctx[tid] = ctx_lens[tid];

    const uint32_t kb_a[2] = { (uint32_t)__cvta_generic_to_shared(kb[0]),
                               (uint32_t)__cvta_generic_to_shared(kb[1]) };
    const uint32_t vb_a[2] = { (uint32_t)__cvta_generic_to_shared(vb[0]),
                               (uint32_t)__cvta_generic_to_shared(vb[1]) };

    for (;;) {
        __syncthreads();                    // buffers / sitem free
        if (tid == 0) *sitem = atomicAdd(&g_item_ctr, 1);
        __syncthreads();
        const int item = *sitem;
        if (item >= NITEMS) break;          // uniform exit

        const int c = item & (MAXC - 1);
        const int g = (item >> 6) & (G - 1);
        const int b = item >> 9;

        const int ctx   = sctx[b];
        const int start = c * CS;
        if (start >= ctx) continue;         // uniform skip
        const int npos = min(CS, ctx - start);
        const int nc   = (ctx + CS - 1) / CS;

        const int blkid = btab[b * MAXB + (start >> 8)];
        const size_t rowbase = (size_t)blkid * BLK + (start & (BLK - 1));
        const float4* kbase = (const float4*)kcache + rowbase * PSTR4 + g * (D / 4);
        const float4* vbase = (const float4*)vcache + rowbase * PSTR4 + g * (D / 4);

        const int lastLocal = (slot_map[b] >= 0) ? (ctx - 1 - start) : -1000000;
        const float4* knp = (const float4*)knew + (size_t)(b * G + g) * (D / 4);
        const float4* vnp = (const float4*)vnew + (size_t)(b * G + g) * (D / 4);

        const int ntiles = (npos + TS - 1) / TS;   // 1 or 2

        // prologue: KV tile 0 -> buffers 0
        {
            const int rows = min(TS, npos);
            #pragma unroll
            for (int j = 0; j < 8; ++j) {
                int idx = tid + 128 * j;
                int row = idx >> 5, cc = idx & 31;
                if (row < rows) {
                    uint32_t off = (uint32_t)((row * 32 + (cc ^ row)) * 16);
                    cp16(kb_a[0] + off, kbase + (size_t)row * PSTR4 + cc);
                    cp16(vb_a[0] + off, vbase + (size_t)row * PSTR4 + cc);
                }
            }
            cp_commit();
        }

        // q into smem, pre-scaled, layout [chunk][head]
        {
            const float4* qb = (const float4*)q + (size_t)(b * NHEADS + g * RQ) * (D / 4);
            int cc = tid >> 2, h = tid & 3;
            float4 t4 = qb[h * 32 + cc];
            t4.x *= QK_SCALE; t4.y *= QK_SCALE; t4.z *= QK_SCALE; t4.w *= QK_SCALE;
            qsm[cc * 4 + h] = t4;
        }

        float4 acc0 = make_float4(0.f, 0.f, 0.f, 0.f);
        float4 acc1 = acc0, acc2 = acc0, acc3 = acc0;
        float m_run = NEG_INF, l_run = 0.f;

        for (int t = 0; t < ntiles; ++t) {
            const int t0 = t * TS;
            const int cur = t & 1;

            __syncthreads();   // (A) tile t-1 buffers & pt free; q/kv(0) stores visible

            if (t + 1 < ntiles) {
                const int t1 = t0 + TS;
                const int rows = min(TS, npos - t1);
                #pragma unroll
                for (int j = 0; j < 8; ++j) {
                    int idx = tid + 128 * j;
                    int row = idx >> 5, cc = idx & 31;
                    if (row < rows) {
                        uint32_t off = (uint32_t)((row * 32 + (cc ^ row)) * 16);
                        cp16(kb_a[cur ^ 1] + off, kbase + (size_t)(t1 + row) * PSTR4 + cc);
                        cp16(vb_a[cur ^ 1] + off, vbase + (size_t)(t1 + row) * PSTR4 + cc);
                    }
                }
            }
            cp_commit();        // unconditional: wait<1> == "KV(t) done"
            cp_wait<1>();
            __syncthreads();    // (B) KV(t) visible CTA-wide

            const int fr = lastLocal - t0;
            if (fr >= 0 && fr < TS) {
                if (tid < 32) {
                    kb[cur][fr * 32 + (tid ^ fr)] = knp[tid];
                    vb[cur][fr * 32 + (tid ^ fr)] = vnp[tid];
                }
                __syncthreads();
            }

            // ---- score: warp = head, lane = position ----
            const int pvn = min(TS, npos - t0);
            float s = NEG_INF;
            {
                const float4* krow = kb[cur] + lane * 32;
                float a = 0.f;
                #pragma unroll 8
                for (int cc = 0; cc < 32; ++cc) {
                    float4 k4 = krow[cc ^ lane];
                    float4 q4 = qsm[cc * 4 + warp];
                    a += k4.x * q4.x + k4.y * q4.y + k4.z * q4.z + k4.w * q4.w;
                }
                if (lane < pvn) s = a;
            }

            float mt = s;
            #pragma unroll
            for (int off = 16; off > 0; off >>= 1)
                mt = fmaxf(mt, __shfl_xor_sync(0xffffffffu, mt, off));

            const float mn = fmaxf(m_run, mt);
            const float al = __expf(m_run - mn);
            m_run = mn;

            const float e = __expf(s - mn);
            ((float*)pt)[lane * 4 + warp] = e;

            float lt = e;
            #pragma unroll
            for (int off = 16; off > 0; off >>= 1)
                lt += __shfl_xor_sync(0xffffffffu, lt, off);
            l_run = l_run * al + lt;

            if (lane == 0) red[warp] = al;
            __syncthreads();    // (C) pt + al visible

            // ---- PV: warp w owns positions w, w+4, ... ----
            {
                const float al0 = red[0], al1 = red[1], al2 = red[2], al3 = red[3];
                acc0.x *= al0; acc0.y *= al0; acc0.z *= al0; acc0.w *= al0;
                acc1.x *= al1; acc1.y *= al1; acc1.z *= al1; acc1.w *= al1;
                acc2.x *= al2; acc2.y *= al2; acc2.z *= al2; acc2.w *= al2;
                acc3.x *= al3; acc3.y *= al3; acc3.z *= al3; acc3.w *= al3;

                #pragma unroll 8
                for (int p = warp; p < pvn; p += 4) {
                    float4 v4 = vb[cur][p * 32 + (lane ^ p)];
                    float4 p4 = pt[p];
                    acc0.x += p4.x * v4.x; acc0.y += p4.x * v4.y;
                    acc0.z += p4.x * v4.z; acc0.w += p4.x * v4.w;
                    acc1.x += p4.y * v4.x; acc1.y += p4.y * v4.y;
                    acc1.z += p4.y * v4.z; acc1.w += p4.y * v4.w;
                    acc2.x += p4.z * v4.x; acc2.y += p4.z * v4.y;
                    acc2.z += p4.z * v4.z; acc2.w += p4.z * v4.w;
                    acc3.x += p4.w * v4.x; acc3.y += p4.w * v4.y;
                    acc3.z += p4.w * v4.z; acc3.w += p4.w * v4.w;
                }
            }
        }

        // ---- write split-KV partials ----
        const size_t pidx = ((size_t)(b * G + g) * MAXC + c) * RQ;
        if (lane == 0) {
            g_pm[pidx + warp] = m_run;
            g_pl[pidx + warp] = l_run;
        }

        cp_wait<0>();
        __syncthreads();
        float4* ab = sm4;   // reuse K bufs: [warp][head][lane] float4
        ab[(warp * 4 + 0) * 32 + lane] = acc0;
        ab[(warp * 4 + 1) * 32 + lane] = acc1;
        ab[(warp * 4 + 2) * 32 + lane] = acc2;
        ab[(warp * 4 + 3) * 32 + lane] = acc3;
        __syncthreads();

        const float* abf = (const float*)ab;
        #pragma unroll
        for (int e = tid; e < RQ * D; e += 128) {
            int h = e >> 7, d = e & 127;
            float A = abf[(0 * 4 + h) * 128 + d] + abf[(1 * 4 + h) * 128 + d]
                    + abf[(2 * 4 + h) * 128 + d] + abf[(3 * 4 + h) * 128 + d];
            g_pacc[(pidx + h) * D + d] = A;
        }

        // ---- completion handshake: last CTA for (b,g) combines ----
        __threadfence();
        __syncthreads();
        if (tid == 0) {
            int prev = atomicAdd(&g_done[b * G + g], 1);
            *sitem = (prev == nc - 1) ? 1 : 0;
        }
        __syncthreads();
        if (*sitem) {
            __threadfence();   // acquire side: other CTAs' partials now visible (L2)
            // warp w combines head w; lane covers d = lane + 32k, k=0..3
            const size_t base = ((size_t)(b * G + g) * MAXC) * RQ + warp;
            float M = NEG_INF, L = 0.f;
            float A0 = 0.f, A1 = 0.f, A2 = 0.f, A3 = 0.f;
            for (int c0 = 0; c0 < nc; c0 += 16) {
                float mv[16], lv[16], a0[16], a1[16], a2[16], a3[16];
                #pragma unroll
                for (int j = 0; j < 16; ++j) {
                    const int cc = c0 + j;
                    if (cc < nc) {
                        const size_t p = base + (size_t)cc * RQ;
                        mv[j] = __ldcg(&g_pm[p]);
                        lv[j] = __ldcg(&g_pl[p]);
                        const float* ap = &g_pacc[p * D];
                        a0[j] = __ldcg(ap + lane);
                        a1[j] = __ldcg(ap + lane + 32);
                        a2[j] = __ldcg(ap + lane + 64);
                        a3[j] = __ldcg(ap + lane + 96);
                    } else {
                        mv[j] = NEG_INF; lv[j] = 0.f;
                        a0[j] = a1[j] = a2[j] = a3[j] = 0.f;
                    }
                }
                float Mt = mv[0];
                #pragma unroll
                for (int j = 1; j < 16; ++j) Mt = fmaxf(Mt, mv[j]);
                const float Mn = fmaxf(M, Mt);
                const float sc = __expf(M - Mn);
                L *= sc; A0 *= sc; A1 *= sc; A2 *= sc; A3 *= sc;
                #pragma unroll
                for (int j = 0; j < 16; ++j) {
                    const float e = __expf(mv[j] - Mn);
                    L  += e * lv[j];
                    A0 += e * a0[j];
                    A1 += e * a1[j];
                    A2 += e * a2[j];
                    A3 += e * a3[j];
                }
                M = Mn;
            }
            const float inv = 1.0f / L;
            float* op = out + ((size_t)b * NHEADS + g * RQ + warp) * D;
            op[lane]      = A0 * inv;
            op[lane + 32] = A1 * inv;
            op[lane + 64] = A2 * inv;
            op[lane + 96] = A3 * inv;
        }
    }
}

extern "C" void kernel_launch(void* const* d_in, const int* in_sizes, int n_in,
                              void* d_out, int out_size)
{
    const float* q    = (const float*)d_in[0];
    const float* k    = (const float*)d_in[1];
    const float* v    = (const float*)d_in[2];
    const float* kc   = (const float*)d_in[3];
    const float* vc   = (const float*)d_in[4];
    const int*   ctx  = (const int*)d_in[5];
    const int*   btab = (const int*)d_in[6];
    const int*   smap = (const int*)d_in[7];
    float* out = (float*)d_out;

    static int smem_set = 0;
    if (!smem_set) {
        cudaFuncSetAttribute(attn_persist_kernel,
                             cudaFuncAttributeMaxDynamicSharedMemorySize, SMEM_BYTES);
        smem_set = 1;
    }

    reset_kernel<<<1, 128>>>();
    attn_persist_kernel<<<NCTAS, 128, SMEM_BYTES>>>(q, k, v, kc, vc, ctx, btab, smap, out);
}

// round 10
// speedup vs baseline: 1.2084x; 1.0869x over previous
#include <cuda_runtime.h>
#include <math.h>
#include <stdint.h>

#define BATCH   16
#define NHEADS  32
#define G       8      // kv heads
#define RQ      4      // query heads per kv head
#define D       128
#define BLK     256    // cache block size (fixed by layout)
#define MAXB    16     // cache blocks per sequence
#define CS      64     // positions per chunk CTA
#define MAXC    64     // max chunks per sequence (4096/64)
#define TS      32     // positions per tile
#define PSTR4   (G * (D / 4))   // float4 stride between positions = 256
#define NEG_INF (-1e30f)
#define QK_SCALE 0.08838834764831845f  // 1/sqrt(128)

// split-KV partial results: [B, G, chunk, rq]
__device__ float g_pm  [BATCH * G * MAXC * RQ];
__device__ float g_pl  [BATCH * G * MAXC * RQ];
__device__ float g_pacc[BATCH * G * MAXC * RQ * D];

// smem layout (float4 units):
//   [0,    1024)  K buf (32 rows x 32 f4, row-XOR swizzled)  16KB
//   [1024, 2048)  V buf                                       16KB
//   [2048, 2176)  q   [chunk][head] float4, pre-scaled
//   [2176, 2208)  pt  [pos] float4 = 4 heads' exp weights
//   [2208, 2209)  red scratch (al[4])
#define KB_F4    0
#define VB_F4    1024
#define QSM_F4   2048
#define PT_F4    2176
#define RED_F4   2208
#define SMEM_F4  2209
#define SMEM_BYTES (SMEM_F4 * 16)   // 35344 B

__global__ __launch_bounds__(128, 4)
void attn_chunk_kernel(const float* __restrict__ q,
                       const float* __restrict__ knew,
                       const float* __restrict__ vnew,
                       const float* __restrict__ kcache,
                       const float* __restrict__ vcache,
                       const int*   __restrict__ ctx_lens,
                       const int*   __restrict__ btab,
                       const int*   __restrict__ slot_map)
{
    const int c = blockIdx.x;   // chunk (CS positions)
    const int g = blockIdx.y;   // kv head
    const int b = blockIdx.z;   // sequence

    const int ctx   = __ldg(&ctx_lens[b]);
    const int start = c * CS;
    if (start >= ctx) return;
    const int npos = min(CS, ctx - start);

    extern __shared__ float4 sm4[];
    float4* kbuf = sm4 + KB_F4;
    float4* vbuf = sm4 + VB_F4;
    float4* qsm  = sm4 + QSM_F4;
    float4* pt   = sm4 + PT_F4;
    float*  red  = (float*)(sm4 + RED_F4);

    const int tid  = threadIdx.x;
    const int lane = tid & 31;
    const int warp = tid >> 5;

    // chunk c sits inside cache block start/BLK at row offset start%BLK
    const int blkid = btab[b * MAXB + (start >> 8)];
    const size_t rowbase = (size_t)blkid * BLK + (start & (BLK - 1));
    const float4* kbase = (const float4*)kcache + rowbase * PSTR4 + g * (D / 4);
    const float4* vbase = (const float4*)vcache + rowbase * PSTR4 + g * (D / 4);

    const int lastLocal = (slot_map[b] >= 0) ? (ctx - 1 - start) : -1000000;
    const float4* knp = (const float4*)knew + (size_t)(b * G + g) * (D / 4);
    const float4* vnp = (const float4*)vnew + (size_t)(b * G + g) * (D / 4);

    const int ntiles = (npos + TS - 1) / TS;   // 1 or 2

    // reg-staging map: j=0..7 -> row = 4*j + warp (each warp owns 8 rows,
    // one contiguous 512B row per LDG.128 across the warp -> coalesced)
    float4 kreg[8], vreg[8];

    // ---- prologue: LDG tile 0 into regs ----
    {
        const int rows = min(TS, npos);
        #pragma unroll
        for (int j = 0; j < 8; ++j) {
            const int row = 4 * j + warp;
            if (row < rows) {
                kreg[j] = kbase[(size_t)row * PSTR4 + lane];
                vreg[j] = vbase[(size_t)row * PSTR4 + lane];
            }
        }
    }

    // q into smem, pre-scaled, layout [chunk][head]
    {
        const float4* qb = (const float4*)q + (size_t)(b * NHEADS + g * RQ) * (D / 4);
        int cc = tid >> 2, h = tid & 3;
        float4 t4 = qb[h * 32 + cc];
        t4.x *= QK_SCALE; t4.y *= QK_SCALE; t4.z *= QK_SCALE; t4.w *= QK_SCALE;
        qsm[cc * 4 + h] = t4;
    }

    // ---- STS tile 0 (swizzled) ----
    {
        const int rows = min(TS, npos);
        #pragma unroll
        for (int j = 0; j < 8; ++j) {
            const int row = 4 * j + warp;
            if (row < rows) {
                kbuf[row * 32 + (lane ^ row)] = kreg[j];
                vbuf[row * 32 + (lane ^ row)] = vreg[j];
            }
        }
    }
    __syncthreads();

    float4 acc0 = make_float4(0.f, 0.f, 0.f, 0.f);
    float4 acc1 = acc0, acc2 = acc0, acc3 = acc0;
    float m_run = NEG_INF, l_run = 0.f;   // per-warp (= per-head) running state

    for (int t = 0; t < ntiles; ++t) {
        const int t0 = t * TS;
        const int pvn = min(TS, npos - t0);

        // fresh-token substitution (rare; uniform branch)
        const int fr = lastLocal - t0;
        if (fr >= 0 && fr < TS) {
            if (tid < 32) {
                kbuf[fr * 32 + (tid ^ fr)] = knp[tid];
                vbuf[fr * 32 + (tid ^ fr)] = vnp[tid];
            }
            __syncthreads();
        }

        // issue LDG for tile t+1 (latency hidden behind score+PV)
        const bool more = (t + 1 < ntiles);
        if (more) {
            const int t1 = t0 + TS;
            const int rows = min(TS, npos - t1);
            #pragma unroll
            for (int j = 0; j < 8; ++j) {
                const int row = 4 * j + warp;
                if (row < rows) {
                    kreg[j] = kbase[(size_t)(t1 + row) * PSTR4 + lane];
                    vreg[j] = vbase[(size_t)(t1 + row) * PSTR4 + lane];
                }
            }
        }

        // ---- score: warp = head, lane = position; 4 accumulators (ILP) ----
        float s = NEG_INF;
        {
            const float4* krow = kbuf + lane * 32;
            float a0 = 0.f, a1 = 0.f, a2 = 0.f, a3 = 0.f;
            #pragma unroll
            for (int cc = 0; cc < 32; cc += 4) {
                float4 k0 = krow[(cc + 0) ^ lane];
                float4 q0 = qsm[(cc + 0) * 4 + warp];
                a0 += k0.x * q0.x + k0.y * q0.y + k0.z * q0.z + k0.w * q0.w;
                float4 k1 = krow[(cc + 1) ^ lane];
                float4 q1 = qsm[(cc + 1) * 4 + warp];
                a1 += k1.x * q1.x + k1.y * q1.y + k1.z * q1.z + k1.w * q1.w;
                float4 k2 = krow[(cc + 2) ^ lane];
                float4 q2 = qsm[(cc + 2) * 4 + warp];
                a2 += k2.x * q2.x + k2.y * q2.y + k2.z * q2.z + k2.w * q2.w;
                float4 k3 = krow[(cc + 3) ^ lane];
                float4 q3 = qsm[(cc + 3) * 4 + warp];
                a3 += k3.x * q3.x + k3.y * q3.y + k3.z * q3.z + k3.w * q3.w;
            }
            if (lane < pvn) s = (a0 + a1) + (a2 + a3);
        }

        // warp-local tile max
        float mt = s;
        #pragma unroll
        for (int off = 16; off > 0; off >>= 1)
            mt = fmaxf(mt, __shfl_xor_sync(0xffffffffu, mt, off));

        const float mn = fmaxf(m_run, mt);
        const float al = __expf(m_run - mn);
        m_run = mn;

        const float e = __expf(s - mn);                  // 0 for invalid lanes
        ((float*)pt)[lane * 4 + warp] = e;

        float lt = e;
        #pragma unroll
        for (int off = 16; off > 0; off >>= 1)
            lt += __shfl_xor_sync(0xffffffffu, lt, off);
        l_run = l_run * al + lt;

        if (lane == 0) red[warp] = al;
        __syncthreads();    // (C) pt + al visible

        // ---- PV: warp w owns positions w, w+4, ... ----
        {
            const float al0 = red[0], al1 = red[1], al2 = red[2], al3 = red[3];
            acc0.x *= al0; acc0.y *= al0; acc0.z *= al0; acc0.w *= al0;
            acc1.x *= al1; acc1.y *= al1; acc1.z *= al1; acc1.w *= al1;
            acc2.x *= al2; acc2.y *= al2; acc2.z *= al2; acc2.w *= al2;
            acc3.x *= al3; acc3.y *= al3; acc3.z *= al3; acc3.w *= al3;

            #pragma unroll 8
            for (int p = warp; p < pvn; p += 4) {
                float4 v4 = vbuf[p * 32 + (lane ^ p)];
                float4 p4 = pt[p];
                acc0.x += p4.x * v4.x; acc0.y += p4.x * v4.y;
                acc0.z += p4.x * v4.z; acc0.w += p4.x * v4.w;
                acc1.x += p4.y * v4.x; acc1.y += p4.y * v4.y;
                acc1.z += p4.y * v4.z; acc1.w += p4.y * v4.w;
                acc2.x += p4.z * v4.x; acc2.y += p4.z * v4.y;
                acc2.z += p4.z * v4.z; acc2.w += p4.z * v4.w;
                acc3.x += p4.w * v4.x; acc3.y += p4.w * v4.y;
                acc3.z += p4.w * v4.z; acc3.w += p4.w * v4.w;
            }
        }

        if (more) {
            __syncthreads();    // (D) all reads of tile t done
            const int t1 = t0 + TS;
            const int rows = min(TS, npos - t1);
            #pragma unroll
            for (int j = 0; j < 8; ++j) {
                const int row = 4 * j + warp;
                if (row < rows) {
                    kbuf[row * 32 + (lane ^ row)] = kreg[j];
                    vbuf[row * 32 + (lane ^ row)] = vreg[j];
                }
            }
            __syncthreads();    // (E) smem now holds tile t+1
        }
    }

    // ---- epilogue: write split-KV partials ----
    const size_t pidx = ((size_t)(b * G + g) * MAXC + c) * RQ;
    if (lane == 0) {
        g_pm[pidx + warp] = m_run;
        g_pl[pidx + warp] = l_run;
    }

    __syncthreads();
    float4* ab = sm4;   // reuse K+V bufs: [warp][head][lane] float4 = 512 f4
    ab[(warp * 4 + 0) * 32 + lane] = acc0;
    ab[(warp * 4 + 1) * 32 + lane] = acc1;
    ab[(warp * 4 + 2) * 32 + lane] = acc2;
    ab[(warp * 4 + 3) * 32 + lane] = acc3;
    __syncthreads();

    const float* abf = (const float*)ab;
    #pragma unroll
    for (int e = tid; e < RQ * D; e += 128) {
        int h = e >> 7, d = e & 127;
        float A = abf[(0 * 4 + h) * 128 + d] + abf[(1 * 4 + h) * 128 + d]
                + abf[(2 * 4 + h) * 128 + d] + abf[(3 * 4 + h) * 128 + d];
        g_pacc[(pidx + h) * D + d] = A;
    }
}

// combine: 512 threads, 4 parallel groups of 16 chunks each; smem merge.
__global__ __launch_bounds__(512)
void attn_combine_kernel(const int* __restrict__ ctx_lens,
                         float* __restrict__ out)
{
    const int h = blockIdx.x;   // 0..31
    const int b = blockIdx.y;   // 0..15
    const int g  = h >> 2;
    const int hh = h & 3;
    const int nc = (ctx_lens[b] + CS - 1) / CS;   // up to 64 chunks
    const int tid = threadIdx.x;
    const int grp = tid >> 7;      // 0..3
    const int d   = tid & 127;

    const size_t base = ((size_t)(b * G + g) * MAXC) * RQ + hh;
    const int lo = grp * 16;

    float mv[16], lv[16], av[16];
    #pragma unroll
    for (int j = 0; j < 16; ++j) {
        const int cc = lo + j;
        if (cc < nc) {
            mv[j] = g_pm[base + (size_t)cc * RQ];
            lv[j] = g_pl[base + (size_t)cc * RQ];
            av[j] = g_pacc[(base + (size_t)cc * RQ) * D + d];
        } else { mv[j] = NEG_INF; lv[j] = 0.f; av[j] = 0.f; }
    }
    float M = mv[0];
    #pragma unroll
    for (int j = 1; j < 16; ++j) M = fmaxf(M, mv[j]);
    float L = 0.f, A = 0.f;
    #pragma unroll
    for (int j = 0; j < 16; ++j) {
        const float e = __expf(mv[j] - M);
        L += e * lv[j];
        A += e * av[j];
    }

    __shared__ float sM[4], sL[4];
    __shared__ float sA[4][D];
    sA[grp][d] = A;
    if (d == 0) { sM[grp] = M; sL[grp] = L; }
    __syncthreads();
    if (grp == 0) {
        float Mt = fmaxf(fmaxf(sM[0], sM[1]), fmaxf(sM[2], sM[3]));
        float Lt = 0.f, At = 0.f;
        #pragma unroll
        for (int k = 0; k < 4; ++k) {
            const float e = __expf(sM[k] - Mt);
            Lt += e * sL[k];
            At += e * sA[k][d];
        }
        out[((size_t)b * NHEADS + h) * D + d] = At / Lt;
    }
}

extern "C" void kernel_launch(void* const* d_in, const int* in_sizes, int n_in,
                              void* d_out, int out_size)
{
    const float* q    = (const float*)d_in[0];
    const float* k    = (const float*)d_in[1];
    const float* v    = (const float*)d_in[2];
    const float* kc   = (const float*)d_in[3];
    const float* vc   = (const float*)d_in[4];
    const int*   ctx  = (const int*)d_in[5];
    const int*   btab = (const int*)d_in[6];
    const int*   smap = (const int*)d_in[7];
    float* out = (float*)d_out;

    dim3 grid(MAXC, G, BATCH);   // 8192 CTAs, ~520 non-empty
    attn_chunk_kernel<<<grid, 128, SMEM_BYTES>>>(q, k, v, kc, vc, ctx, btab, smap);
    attn_combine_kernel<<<dim3(NHEADS, BATCH), 512>>>(ctx, out);
}

// round 11
// speedup vs baseline: 1.5841x; 1.3108x over previous
#include <cuda_runtime.h>
#include <math.h>
#include <stdint.h>

#define BATCH   16
#define NHEADS  32
#define G       8      // kv heads
#define RQ      4      // query heads per kv head
#define D       128
#define BLK     256    // cache block size (fixed by layout)
#define MAXB    16     // cache blocks per sequence
#define CS      64     // positions per chunk CTA
#define MAXC    64     // max chunks per sequence (4096/64)
#define TS      32     // positions per tile
#define PSTR4   (G * (D / 4))   // float4 stride between positions = 256
#define NEG_INF (-1e30f)
#define QK_SCALE 0.08838834764831845f  // 1/sqrt(128)

// split-KV partial results: [B, G, chunk, rq]
__device__ float g_pm  [BATCH * G * MAXC * RQ];
__device__ float g_pl  [BATCH * G * MAXC * RQ];
__device__ float g_pacc[BATCH * G * MAXC * RQ * D];

__device__ __forceinline__ void cp16(uint32_t dst, const void* src) {
    asm volatile("cp.async.cg.shared.global [%0], [%1], 16;" :: "r"(dst), "l"(src));
}
__device__ __forceinline__ void cp_commit() {
    asm volatile("cp.async.commit_group;");
}
template <int N>
__device__ __forceinline__ void cp_wait() {
    asm volatile("cp.async.wait_group %0;" :: "n"(N));
}

// smem layout (float4 units) — SINGLE buffer, 35.3KB -> 6 CTAs/SM:
//   [0,    1024)  K buf (32 rows x 32 f4, row-XOR swizzled)  16KB
//   [1024, 2048)  V buf                                       16KB
//   [2048, 2176)  q   [chunk][head] float4, pre-scaled
//   [2176, 2208)  pt  [pos] float4 = 4 heads' exp weights
//   [2208, 2209)  red scratch (al[4])
#define KB_F4    0
#define VB_F4    1024
#define QSM_F4   2048
#define PT_F4    2176
#define RED_F4   2208
#define SMEM_F4  2209
#define SMEM_BYTES (SMEM_F4 * 16)   // 35344 B

__global__ __launch_bounds__(128, 6)
void attn_chunk_kernel(const float* __restrict__ q,
                       const float* __restrict__ knew,
                       const float* __restrict__ vnew,
                       const float* __restrict__ kcache,
                       const float* __restrict__ vcache,
                       const int*   __restrict__ ctx_lens,
                       const int*   __restrict__ btab,
                       const int*   __restrict__ slot_map)
{
    const int c = blockIdx.x;   // chunk (CS positions)
    const int g = blockIdx.y;   // kv head
    const int b = blockIdx.z;   // sequence

    const int ctx   = __ldg(&ctx_lens[b]);
    const int start = c * CS;
    if (start >= ctx) return;
    const int npos = min(CS, ctx - start);

    extern __shared__ float4 sm4[];
    float4* kbuf = sm4 + KB_F4;
    float4* vbuf = sm4 + VB_F4;
    float4* qsm  = sm4 + QSM_F4;
    float4* pt   = sm4 + PT_F4;
    float*  red  = (float*)(sm4 + RED_F4);

    const int tid  = threadIdx.x;
    const int lane = tid & 31;
    const int warp = tid >> 5;

    // chunk c sits inside cache block start/BLK at row offset start%BLK
    const int blkid = btab[b * MAXB + (start >> 8)];
    const size_t rowbase = (size_t)blkid * BLK + (start & (BLK - 1));
    const float4* kbase = (const float4*)kcache + rowbase * PSTR4 + g * (D / 4);
    const float4* vbase = (const float4*)vcache + rowbase * PSTR4 + g * (D / 4);

    const int lastLocal = (slot_map[b] >= 0) ? (ctx - 1 - start) : -1000000;
    const float4* knp = (const float4*)knew + (size_t)(b * G + g) * (D / 4);
    const float4* vnp = (const float4*)vnew + (size_t)(b * G + g) * (D / 4);

    const uint32_t kb_a = (uint32_t)__cvta_generic_to_shared(kbuf);
    const uint32_t vb_a = (uint32_t)__cvta_generic_to_shared(vbuf);

    const int ntiles = (npos + TS - 1) / TS;   // 1 or 2

    // ---- issue tile 0 immediately (32KB outstanding during q setup) ----
    {
        const int rows = min(TS, npos);
        #pragma unroll
        for (int j = 0; j < 8; ++j) {
            int idx = tid + 128 * j;
            int row = idx >> 5, cc = idx & 31;
            if (row < rows) {
                uint32_t off = (uint32_t)((row * 32 + (cc ^ row)) * 16);
                cp16(kb_a + off, kbase + (size_t)row * PSTR4 + cc);
                cp16(vb_a + off, vbase + (size_t)row * PSTR4 + cc);
            }
        }
        cp_commit();
    }

    // q into smem, pre-scaled, layout [chunk][head]
    {
        const float4* qb = (const float4*)q + (size_t)(b * NHEADS + g * RQ) * (D / 4);
        int cc = tid >> 2, h = tid & 3;
        float4 t4 = qb[h * 32 + cc];
        t4.x *= QK_SCALE; t4.y *= QK_SCALE; t4.z *= QK_SCALE; t4.w *= QK_SCALE;
        qsm[cc * 4 + h] = t4;
    }

    float4 acc0 = make_float4(0.f, 0.f, 0.f, 0.f);
    float4 acc1 = acc0, acc2 = acc0, acc3 = acc0;
    float m_run = NEG_INF, l_run = 0.f;   // per-warp (= per-head) running state

    for (int t = 0; t < ntiles; ++t) {
        const int t0 = t * TS;
        const int pvn = min(TS, npos - t0);

        cp_wait<0>();
        __syncthreads();    // (B) tile t + q visible CTA-wide

        // fresh-token substitution (rare; uniform branch)
        const int fr = lastLocal - t0;
        if (fr >= 0 && fr < TS) {
            if (tid < 32) {
                kbuf[fr * 32 + (tid ^ fr)] = knp[tid];
                vbuf[fr * 32 + (tid ^ fr)] = vnp[tid];
            }
            __syncthreads();
        }

        // ---- score: warp = head, lane = position; 4 accumulators (ILP) ----
        float s = NEG_INF;
        {
            const float4* krow = kbuf + lane * 32;
            float a0 = 0.f, a1 = 0.f, a2 = 0.f, a3 = 0.f;
            #pragma unroll
            for (int cc = 0; cc < 32; cc += 4) {
                float4 k0 = krow[(cc + 0) ^ lane];
                float4 q0 = qsm[(cc + 0) * 4 + warp];
                a0 += k0.x * q0.x + k0.y * q0.y + k0.z * q0.z + k0.w * q0.w;
                float4 k1 = krow[(cc + 1) ^ lane];
                float4 q1 = qsm[(cc + 1) * 4 + warp];
                a1 += k1.x * q1.x + k1.y * q1.y + k1.z * q1.z + k1.w * q1.w;
                float4 k2 = krow[(cc + 2) ^ lane];
                float4 q2 = qsm[(cc + 2) * 4 + warp];
                a2 += k2.x * q2.x + k2.y * q2.y + k2.z * q2.z + k2.w * q2.w;
                float4 k3 = krow[(cc + 3) ^ lane];
                float4 q3 = qsm[(cc + 3) * 4 + warp];
                a3 += k3.x * q3.x + k3.y * q3.y + k3.z * q3.z + k3.w * q3.w;
            }
            if (lane < pvn) s = (a0 + a1) + (a2 + a3);
        }

        // warp-local tile max
        float mt = s;
        #pragma unroll
        for (int off = 16; off > 0; off >>= 1)
            mt = fmaxf(mt, __shfl_xor_sync(0xffffffffu, mt, off));

        const float mn = fmaxf(m_run, mt);
        const float al = __expf(m_run - mn);
        m_run = mn;

        const float e = __expf(s - mn);                  // 0 for invalid lanes
        ((float*)pt)[lane * 4 + warp] = e;

        float lt = e;
        #pragma unroll
        for (int off = 16; off > 0; off >>= 1)
            lt += __shfl_xor_sync(0xffffffffu, lt, off);
        l_run = l_run * al + lt;

        if (lane == 0) red[warp] = al;
        __syncthreads();    // (C) pt + al visible

        // ---- PV: warp w owns positions w, w+4, ... ----
        {
            const float al0 = red[0], al1 = red[1], al2 = red[2], al3 = red[3];
            acc0.x *= al0; acc0.y *= al0; acc0.z *= al0; acc0.w *= al0;
            acc1.x *= al1; acc1.y *= al1; acc1.z *= al1; acc1.w *= al1;
            acc2.x *= al2; acc2.y *= al2; acc2.z *= al2; acc2.w *= al2;
            acc3.x *= al3; acc3.y *= al3; acc3.z *= al3; acc3.w *= al3;

            #pragma unroll 8
            for (int p = warp; p < pvn; p += 4) {
                float4 v4 = vbuf[p * 32 + (lane ^ p)];
                float4 p4 = pt[p];
                acc0.x += p4.x * v4.x; acc0.y += p4.x * v4.y;
                acc0.z += p4.x * v4.z; acc0.w += p4.x * v4.w;
                acc1.x += p4.y * v4.x; acc1.y += p4.y * v4.y;
                acc1.z += p4.y * v4.z; acc1.w += p4.y * v4.w;
                acc2.x += p4.z * v4.x; acc2.y += p4.z * v4.y;
                acc2.z += p4.z * v4.z; acc2.w += p4.z * v4.w;
                acc3.x += p4.w * v4.x; acc3.y += p4.w * v4.y;
                acc3.z += p4.w * v4.z; acc3.w += p4.w * v4.w;
            }
        }

        // issue tile t+1 after all reads of tile t complete
        if (t + 1 < ntiles) {
            __syncthreads();    // (D)
            const int t1 = t0 + TS;
            const int rows = min(TS, npos - t1);
            #pragma unroll
            for (int j = 0; j < 8; ++j) {
                int idx = tid + 128 * j;
                int row = idx >> 5, cc = idx & 31;
                if (row < rows) {
                    uint32_t off = (uint32_t)((row * 32 + (cc ^ row)) * 16);
                    cp16(kb_a + off, kbase + (size_t)(t1 + row) * PSTR4 + cc);
                    cp16(vb_a + off, vbase + (size_t)(t1 + row) * PSTR4 + cc);
                }
            }
            cp_commit();
        }
    }

    // ---- epilogue: write split-KV partials ----
    const size_t pidx = ((size_t)(b * G + g) * MAXC + c) * RQ;
    if (lane == 0) {
        g_pm[pidx + warp] = m_run;
        g_pl[pidx + warp] = l_run;
    }

    __syncthreads();
    float4* ab = sm4;   // reuse K+V bufs: [warp][head][lane] float4 = 512 f4
    ab[(warp * 4 + 0) * 32 + lane] = acc0;
    ab[(warp * 4 + 1) * 32 + lane] = acc1;
    ab[(warp * 4 + 2) * 32 + lane] = acc2;
    ab[(warp * 4 + 3) * 32 + lane] = acc3;
    __syncthreads();

    const float* abf = (const float*)ab;
    #pragma unroll
    for (int e = tid; e < RQ * D; e += 128) {
        int h = e >> 7, d = e & 127;
        float A = abf[(0 * 4 + h) * 128 + d] + abf[(1 * 4 + h) * 128 + d]
                + abf[(2 * 4 + h) * 128 + d] + abf[(3 * 4 + h) * 128 + d];
        g_pacc[(pidx + h) * D + d] = A;
    }
}

// combine: 1024 threads, 8 parallel groups of 8 chunks each; smem merge.
__global__ __launch_bounds__(1024)
void attn_combine_kernel(const int* __restrict__ ctx_lens,
                         float* __restrict__ out)
{
    const int h = blockIdx.x;   // 0..31
    const int b = blockIdx.y;   // 0..15
    const int g  = h >> 2;
    const int hh = h & 3;
    const int nc = (ctx_lens[b] + CS - 1) / CS;   // up to 64 chunks
    const int tid = threadIdx.x;
    const int grp = tid >> 7;      // 0..7
    const int d   = tid & 127;

    const size_t base = ((size_t)(b * G + g) * MAXC) * RQ + hh;
    const int lo = grp * 8;

    float mv[8], lv[8], av[8];
    #pragma unroll
    for (int j = 0; j < 8; ++j) {
        const int cc = lo + j;
        if (cc < nc) {
            mv[j] = g_pm[base + (size_t)cc * RQ];
            lv[j] = g_pl[base + (size_t)cc * RQ];
            av[j] = g_pacc[(base + (size_t)cc * RQ) * D + d];
        } else { mv[j] = NEG_INF; lv[j] = 0.f; av[j] = 0.f; }
    }
    float M = mv[0];
    #pragma unroll
    for (int j = 1; j < 8; ++j) M = fmaxf(M, mv[j]);
    float L = 0.f, A = 0.f;
    #pragma unroll
    for (int j = 0; j < 8; ++j) {
        const float e = __expf(mv[j] - M);
        L += e * lv[j];
        A += e * av[j];
    }

    __shared__ float sM[8], sL[8];
    __shared__ float sA[8][D];
    sA[grp][d] = A;
    if (d == 0) { sM[grp] = M; sL[grp] = L; }
    __syncthreads();
    if (grp == 0) {
        float Mt = sM[0];
        #pragma unroll
        for (int k = 1; k < 8; ++k) Mt = fmaxf(Mt, sM[k]);
        float Lt = 0.f, At = 0.f;
        #pragma unroll
        for (int k = 0; k < 8; ++k) {
            const float e = __expf(sM[k] - Mt);
            Lt += e * sL[k];
            At += e * sA[k][d];
        }
        out[((size_t)b * NHEADS + h) * D + d] = At / Lt;
    }
}

extern "C" void kernel_launch(void* const* d_in, const int* in_sizes, int n_in,
                              void* d_out, int out_size)
{
    const float* q    = (const float*)d_in[0];
    const float* k    = (const float*)d_in[1];
    const float* v    = (const float*)d_in[2];
    const float* kc   = (const float*)d_in[3];
    const float* vc   = (const float*)d_in[4];
    const int*   ctx  = (const int*)d_in[5];
    const int*   btab = (const int*)d_in[6];
    const int*   smap = (const int*)d_in[7];
    float* out = (float*)d_out;

    dim3 grid(MAXC, G, BATCH);   // 8192 CTAs, ~520 non-empty
    attn_chunk_kernel<<<grid, 128, SMEM_BYTES>>>(q, k, v, kc, vc, ctx, btab, smap);
    attn_combine_kernel<<<dim3(NHEADS, BATCH), 1024>>>(ctx, out);
}